// round 17
// baseline (speedup 1.0000x reference)
#include <cuda_runtime.h>
#include <cuda_fp16.h>
#include <math.h>

#define NN 100000
#define EE 3200000
#define GG 1024
#define NREP 64   // stats replicas
#define GEMM_BLOCKS 782   // ceil(NN/128)

// XOR-phase swizzle for the 128x64 X tile: row-group (r>>3)&3 shifts columns by 8 floats
#define XPH(r) ((((r) >> 3) & 3) * 8)
#define XC(r, c) ((((c) + XPH(r)) & 63))

// ---------------- scratch (no allocations allowed) ----------------
__device__ __half g_z16[NN * 64];     // fp16 gather operand (z of current layer)
__device__ float  g_u[NN * 64];       // u = relu(z+agg+b1), fp32
__device__ float  g_statsP[NREP * 128]; // replicated [sum(64), sumsq(64)]
__device__ float  g_W2p[64 * 64];
__device__ float  g_b2p[64];
__device__ int    g_cur[NN];          // degree counter
__device__ int    g_off[NN + 1];      // CSR offsets
__device__ int    g_col[EE];          // CSR column (src) list
__device__ int    g_rank[EE];         // per-edge rank within its dst bucket

struct alignas(8) H4 { __half2 a, b; };
struct alignas(16) H8 { __half2 a, b, c, d; };

__device__ __forceinline__ void red_add_v4(float* addr, float4 v) {
    asm volatile("red.global.add.v4.f32 [%0], {%1, %2, %3, %4};"
                 :: "l"(addr), "f"(v.x), "f"(v.y), "f"(v.z), "f"(v.w)
                 : "memory");
}
__device__ __forceinline__ void red_add_f(float* addr, float v) {
    asm volatile("red.global.add.f32 [%0], %1;" :: "l"(addr), "f"(v) : "memory");
}
__device__ __forceinline__ float4 h4_to_f4(H4 p) {
    float2 lo = __half22float2(p.a);
    float2 hi = __half22float2(p.b);
    return make_float4(lo.x, lo.y, hi.x, hi.y);
}

// ====== hist + rank capture: rank[e] = old count of dst[e] ======
__global__ __launch_bounds__(256) void hist_kernel(const int4* __restrict__ dst4) {
    int e = blockIdx.x * 256 + threadIdx.x;   // over EE/4
    if (e < EE / 4) {
        int4 d = __ldg(dst4 + e);
        int4 r;
        r.x = atomicAdd(&g_cur[d.x], 1);
        r.y = atomicAdd(&g_cur[d.y], 1);
        r.z = atomicAdd(&g_cur[d.z], 1);
        r.w = atomicAdd(&g_cur[d.w], 1);
        ((int4*)g_rank)[e] = r;
    }
}

// scan + zero statsP + zero xg (absorbs memset nodes)
__global__ __launch_bounds__(1024) void scan_kernel(float* __restrict__ xg) {
    for (int i = threadIdx.x; i < NREP * 128; i += 1024) g_statsP[i] = 0.f;
    for (int i = threadIdx.x; i < GG * 64; i += 1024) xg[i] = 0.f;

    __shared__ int part[1024];
    const int C = (NN + 1023) / 1024;   // 98
    const int t = threadIdx.x;
    const int begin = t * C;
    const int end = min(begin + C, NN);
    int s = 0;
    for (int i = begin; i < end; i++) s += g_cur[i];
    part[t] = s;
    __syncthreads();
    for (int d = 1; d < 1024; d <<= 1) {
        int v = (t >= d) ? part[t - d] : 0;
        __syncthreads();
        part[t] += v;
        __syncthreads();
    }
    int run = (t == 0) ? 0 : part[t - 1];
    for (int i = begin; i < end; i++) {
        int d = g_cur[i];
        g_off[i] = run;
        run += d;
    }
    if (t == 1023) g_off[NN] = run;
}

// ================= shared 8x8 GEMM core (128 threads, 128x64 tile, swizzled Xs) =================
// stage 128x64 X tile: 2048 float4s over 128 threads -> 16 iterations
__device__ __forceinline__ void stage_X(float (*Xs)[64], const float* __restrict__ X,
                                        int row0, int k0, int K, int n, int tid) {
#pragma unroll
    for (int t = 0; t < 16; t++) {
        int fidx = t * 128 + tid;
        int r = fidx >> 4;
        int c = (fidx & 15) * 4;
        float4 v = make_float4(0.f, 0.f, 0.f, 0.f);
        int row = row0 + r;
        if (row < n) v = *(const float4*)(X + (size_t)row * K + k0 + c);
        *(float4*)&Xs[r][XC(r, c)] = v;
    }
}
// stage 64x64 W tile: 1024 float4s over 128 threads -> 8 iterations (no swizzle needed)
__device__ __forceinline__ void stage_W(float (*Ws)[64], const float* __restrict__ W,
                                        int k0, int tid) {
#pragma unroll
    for (int t = 0; t < 8; t++) {
        int fidx = t * 128 + tid;
        int kk = fidx >> 4;
        int c = (fidx & 15) * 4;
        *(float4*)&Ws[kk][c] = *(const float4*)(W + (size_t)(k0 + kk) * 64 + c);
    }
}
__device__ __forceinline__ void mma88(float acc[8][8], const float (*Xs)[64],
                                      const float (*Ws)[64], int row8, int col8) {
    const int ph = XPH(row8);   // same group for rows row8..row8+7
#pragma unroll
    for (int kk = 0; kk < 64; kk += 4) {
        const int kx = (kk + ph) & 63;  // swizzled, float4-aligned, wrap-safe
        float4 wa[4], wb[4];
#pragma unroll
        for (int k2 = 0; k2 < 4; k2++) {
            wa[k2] = *(const float4*)&Ws[kk + k2][col8];
            wb[k2] = *(const float4*)&Ws[kk + k2][col8 + 4];
        }
#pragma unroll
        for (int r = 0; r < 8; r++) {
            float4 xv = *(const float4*)&Xs[row8 + r][kx];
            acc[r][0] += xv.x * wa[0].x + xv.y * wa[1].x + xv.z * wa[2].x + xv.w * wa[3].x;
            acc[r][1] += xv.x * wa[0].y + xv.y * wa[1].y + xv.z * wa[2].y + xv.w * wa[3].y;
            acc[r][2] += xv.x * wa[0].z + xv.y * wa[1].z + xv.z * wa[2].z + xv.w * wa[3].z;
            acc[r][3] += xv.x * wa[0].w + xv.y * wa[1].w + xv.z * wa[2].w + xv.w * wa[3].w;
            acc[r][4] += xv.x * wb[0].x + xv.y * wb[1].x + xv.z * wb[2].x + xv.w * wb[3].x;
            acc[r][5] += xv.x * wb[0].y + xv.y * wb[1].y + xv.z * wb[2].y + xv.w * wb[3].y;
            acc[r][6] += xv.x * wb[0].z + xv.y * wb[1].z + xv.z * wb[2].z + xv.w * wb[3].z;
            acc[r][7] += xv.x * wb[0].w + xv.y * wb[1].w + xv.z * wb[2].w + xv.w * wb[3].w;
        }
    }
}

// ---------------- gemm0 (z16 = X @ W1_0, fp16 out) + atomic-free scatter tail ----------------
__global__ __launch_bounds__(128, 4) void gemm0_scatter(const float* __restrict__ X,
                                                        const float* __restrict__ W,
                                                        __half* __restrict__ out16, int n,
                                                        const int4* __restrict__ src4,
                                                        const int4* __restrict__ dst4) {
    __shared__ float Xs[128][64];
    __shared__ float Ws[64][64];
    const int tid  = threadIdx.x;
    const int row0 = blockIdx.x * 128;
    const int col8 = (tid & 7) * 8;
    const int row8 = (tid >> 3) * 8;

    float acc[8][8];
#pragma unroll
    for (int r = 0; r < 8; r++)
#pragma unroll
        for (int c = 0; c < 8; c++) acc[r][c] = 0.f;

    for (int k0 = 0; k0 < 128; k0 += 64) {
        stage_X(Xs, X, row0, k0, 128, n, tid);
        stage_W(Ws, W, k0, tid);
        __syncthreads();
        mma88(acc, Xs, Ws, row8, col8);
        __syncthreads();
    }
#pragma unroll
    for (int r = 0; r < 8; r++) {
        int row = row0 + row8 + r;
        if (row < n) {
            H8 p;
            p.a = __floats2half2_rn(acc[r][0], acc[r][1]);
            p.b = __floats2half2_rn(acc[r][2], acc[r][3]);
            p.c = __floats2half2_rn(acc[r][4], acc[r][5]);
            p.d = __floats2half2_rn(acc[r][6], acc[r][7]);
            *(H8*)(out16 + (size_t)row * 64 + col8) = p;
        }
    }

    // ---- scatter tail: this block handles 1024 int4-edges, atomic-free ----
#pragma unroll
    for (int t = 0; t < 8; t++) {
        int e = blockIdx.x * 1024 + t * 128 + tid;
        if (e < EE / 4) {
            int4 s = __ldg(src4 + e);
            int4 d = __ldg(dst4 + e);
            int4 r = __ldg(((const int4*)g_rank) + e);
            g_col[__ldg(&g_off[d.x]) + r.x] = s.x;
            g_col[__ldg(&g_off[d.y]) + r.y] = s.y;
            g_col[__ldg(&g_off[d.z]) + r.z] = s.z;
            g_col[__ldg(&g_off[d.w]) + r.w] = s.w;
        }
    }
}

// --------- fused middle: z' = relu(U @ W2p + b2p) @ W1_1 -> fp16 ---------
__global__ __launch_bounds__(128, 4) void gemm_mid(const float* __restrict__ U,
                                                   const float* __restrict__ W2p,
                                                   const float* __restrict__ b2p,
                                                   const float* __restrict__ W1_1,
                                                   __half* __restrict__ out16, int n) {
    __shared__ float Xs[128][64];
    __shared__ float Ws[64][64];
    const int tid  = threadIdx.x;
    const int row0 = blockIdx.x * 128;
    const int col8 = (tid & 7) * 8;
    const int row8 = (tid >> 3) * 8;
    const int ph = XPH(row8);

    float acc[8][8];
#pragma unroll
    for (int r = 0; r < 8; r++)
#pragma unroll
        for (int c = 0; c < 8; c++) acc[r][c] = 0.f;

    stage_X(Xs, U, row0, 0, 64, n, tid);
    stage_W(Ws, W2p, 0, tid);
    __syncthreads();
    mma88(acc, Xs, Ws, row8, col8);
    __syncthreads();   // all reads of Xs done; safe to overwrite with h

    float4 bb0 = *(const float4*)(b2p + col8);
    float4 bb1 = *(const float4*)(b2p + col8 + 4);
#pragma unroll
    for (int r = 0; r < 8; r++) {
        float4 h0, h1;
        h0.x = fmaxf(acc[r][0] + bb0.x, 0.f);
        h0.y = fmaxf(acc[r][1] + bb0.y, 0.f);
        h0.z = fmaxf(acc[r][2] + bb0.z, 0.f);
        h0.w = fmaxf(acc[r][3] + bb0.w, 0.f);
        h1.x = fmaxf(acc[r][4] + bb1.x, 0.f);
        h1.y = fmaxf(acc[r][5] + bb1.y, 0.f);
        h1.z = fmaxf(acc[r][6] + bb1.z, 0.f);
        h1.w = fmaxf(acc[r][7] + bb1.w, 0.f);
        // swizzled writeback (rows row8+r are in row8's group; phase = ph)
        *(float4*)&Xs[row8 + r][(col8 + ph) & 63] = h0;
        *(float4*)&Xs[row8 + r][(col8 + 4 + ph) & 63] = h1;
#pragma unroll
        for (int c = 0; c < 8; c++) acc[r][c] = 0.f;
    }
    stage_W(Ws, W1_1, 0, tid);
    __syncthreads();
    mma88(acc, Xs, Ws, row8, col8);

#pragma unroll
    for (int r = 0; r < 8; r++) {
        int row = row0 + row8 + r;
        if (row < n) {
            H8 p;
            p.a = __floats2half2_rn(acc[r][0], acc[r][1]);
            p.b = __floats2half2_rn(acc[r][2], acc[r][3]);
            p.c = __floats2half2_rn(acc[r][4], acc[r][5]);
            p.d = __floats2half2_rn(acc[r][6], acc[r][7]);
            *(H8*)(out16 + (size_t)row * 64 + col8) = p;
        }
    }
}

// --------- final: hout = relu(U @ W2p + b2p), + pool ---------
__global__ __launch_bounds__(128, 4) void gemm_final(const float* __restrict__ U,
                                                     const float* __restrict__ W2p,
                                                     const float* __restrict__ b2p,
                                                     float* __restrict__ out,
                                                     const int* __restrict__ batch,
                                                     float* __restrict__ xg, int n) {
    __shared__ float Xs[128][64];
    __shared__ float Ws[64][64];
    const int tid  = threadIdx.x;
    const int row0 = blockIdx.x * 128;
    const int col8 = (tid & 7) * 8;
    const int row8 = (tid >> 3) * 8;

    float acc[8][8];
#pragma unroll
    for (int r = 0; r < 8; r++)
#pragma unroll
        for (int c = 0; c < 8; c++) acc[r][c] = 0.f;

    stage_X(Xs, U, row0, 0, 64, n, tid);
    stage_W(Ws, W2p, 0, tid);
    __syncthreads();
    mma88(acc, Xs, Ws, row8, col8);

    float4 bb0 = *(const float4*)(b2p + col8);
    float4 bb1 = *(const float4*)(b2p + col8 + 4);
#pragma unroll
    for (int r = 0; r < 8; r++) {
        int row = row0 + row8 + r;
        if (row < n) {
            float4 o0, o1;
            o0.x = fmaxf(acc[r][0] + bb0.x, 0.f);
            o0.y = fmaxf(acc[r][1] + bb0.y, 0.f);
            o0.z = fmaxf(acc[r][2] + bb0.z, 0.f);
            o0.w = fmaxf(acc[r][3] + bb0.w, 0.f);
            o1.x = fmaxf(acc[r][4] + bb1.x, 0.f);
            o1.y = fmaxf(acc[r][5] + bb1.y, 0.f);
            o1.z = fmaxf(acc[r][6] + bb1.z, 0.f);
            o1.w = fmaxf(acc[r][7] + bb1.w, 0.f);
            *(float4*)(out + (size_t)row * 64 + col8) = o0;
            *(float4*)(out + (size_t)row * 64 + col8 + 4) = o1;
            int b = __ldg(batch + row);
            red_add_v4(xg + (size_t)b * 64 + col8, o0);
            red_add_v4(xg + (size_t)b * 64 + col8 + 4, o1);
        }
    }
}

// ========== fused gather(fp16) + self + bias + relu + stats ==========
__global__ __launch_bounds__(256) void gather_post(const __half* __restrict__ z16,
                                                   const float* __restrict__ b1,
                                                   float* __restrict__ u) {
    __shared__ float ssum[8][64];
    __shared__ float ssq[8][64];
    const int warp = threadIdx.x >> 5;
    const int lane = threadIdx.x & 31;
    const int n = blockIdx.x * 8 + warp;
    const int half = lane >> 4;           // 0 or 1
    const int c4 = (lane & 15) * 4;       // feature offset (halves)

    const int beg = __ldg(&g_off[n]);
    const int endo = __ldg(&g_off[n + 1]);

    float4 acc = make_float4(0.f, 0.f, 0.f, 0.f);
    int j = beg + half;
    for (; j + 6 < endo; j += 8) {
        int s0 = __ldg(&g_col[j]);
        int s1 = __ldg(&g_col[j + 2]);
        int s2 = __ldg(&g_col[j + 4]);
        int s3 = __ldg(&g_col[j + 6]);
        float4 v0 = h4_to_f4(*(const H4*)(z16 + (size_t)s0 * 64 + c4));
        float4 v1 = h4_to_f4(*(const H4*)(z16 + (size_t)s1 * 64 + c4));
        float4 v2 = h4_to_f4(*(const H4*)(z16 + (size_t)s2 * 64 + c4));
        float4 v3 = h4_to_f4(*(const H4*)(z16 + (size_t)s3 * 64 + c4));
        acc.x += (v0.x + v1.x) + (v2.x + v3.x);
        acc.y += (v0.y + v1.y) + (v2.y + v3.y);
        acc.z += (v0.z + v1.z) + (v2.z + v3.z);
        acc.w += (v0.w + v1.w) + (v2.w + v3.w);
    }
#pragma unroll 1
    for (; j < endo; j += 2) {
        int s0 = __ldg(&g_col[j]);
        float4 v0 = h4_to_f4(*(const H4*)(z16 + (size_t)s0 * 64 + c4));
        acc.x += v0.x; acc.y += v0.y; acc.z += v0.z; acc.w += v0.w;
    }
    acc.x += __shfl_down_sync(0xffffffffu, acc.x, 16);
    acc.y += __shfl_down_sync(0xffffffffu, acc.y, 16);
    acc.z += __shfl_down_sync(0xffffffffu, acc.z, 16);
    acc.w += __shfl_down_sync(0xffffffffu, acc.w, 16);

    if (half == 0) {
        float4 zz = h4_to_f4(*(const H4*)(z16 + (size_t)n * 64 + c4));
        float4 bb = *(const float4*)(b1 + c4);
        float4 o;
        o.x = fmaxf(zz.x + acc.x + bb.x, 0.f);
        o.y = fmaxf(zz.y + acc.y + bb.y, 0.f);
        o.z = fmaxf(zz.z + acc.z + bb.z, 0.f);
        o.w = fmaxf(zz.w + acc.w + bb.w, 0.f);
        *(float4*)(u + (size_t)n * 64 + c4) = o;
        *(float4*)&ssum[warp][c4] = o;
        float4 q = make_float4(o.x * o.x, o.y * o.y, o.z * o.z, o.w * o.w);
        *(float4*)&ssq[warp][c4] = q;
    }
    __syncthreads();
    const int tid = threadIdx.x;
    const int rep = blockIdx.x & (NREP - 1);
    if (tid < 64) {
        float s = 0.f;
#pragma unroll
        for (int w = 0; w < 8; w++) s += ssum[w][tid];
        red_add_f(&g_statsP[rep * 128 + tid], s);
    } else if (tid < 128) {
        int f = tid - 64;
        float s = 0.f;
#pragma unroll
        for (int w = 0; w < 8; w++) s += ssq[w][f];
        red_add_f(&g_statsP[rep * 128 + 64 + f], s);
    }
}

// ---------------- fold BN into W2/b2; re-zero statsP for next use ----------------
__global__ void bn_finalize(const float* __restrict__ gam, const float* __restrict__ be,
                            const float* __restrict__ W2, const float* __restrict__ b2) {
    const int j = threadIdx.x & 63;
    const int q = threadIdx.x >> 6;  // 0..3
    __shared__ float scale[64], shift[64];
    __shared__ float pa[4][64];
    if (q == 0) {
        float sum = 0.f, sq = 0.f;
#pragma unroll 8
        for (int r = 0; r < NREP; r++) {
            sum += g_statsP[r * 128 + j];
            sq  += g_statsP[r * 128 + 64 + j];
        }
        const float inv_n = 1.0f / (float)NN;
        float mu = sum * inv_n;
        float var = sq * inv_n - mu * mu;
        float sc = gam[j] * rsqrtf(var + 1e-5f);
        scale[j] = sc;
        shift[j] = be[j] - mu * sc;
    }
    __syncthreads();
    for (int i = threadIdx.x; i < NREP * 128; i += 256) g_statsP[i] = 0.f;

    float acc = 0.f;
#pragma unroll
    for (int t = 0; t < 16; t++) {
        int k = q * 16 + t;
        float w = W2[k * 64 + j];
        g_W2p[k * 64 + j] = scale[k] * w;
        acc += shift[k] * w;
    }
    pa[q][j] = acc;
    __syncthreads();
    if (q == 0) g_b2p[j] = b2[j] + pa[0][j] + pa[1][j] + pa[2][j] + pa[3][j];
}

extern "C" void kernel_launch(void* const* d_in, const int* in_sizes, int n_in,
                              void* d_out, int out_size) {
    const float* x     = (const float*)d_in[0];
    const int*   ei    = (const int*)d_in[1];
    const int*   batch = (const int*)d_in[2];
    const float* W1_0  = (const float*)d_in[3];
    const float* b1_0  = (const float*)d_in[4];
    const float* g_0   = (const float*)d_in[5];
    const float* be_0  = (const float*)d_in[6];
    const float* W2_0  = (const float*)d_in[7];
    const float* b2_0  = (const float*)d_in[8];
    const float* W1_1  = (const float*)d_in[9];
    const float* b1_1  = (const float*)d_in[10];
    const float* g_1   = (const float*)d_in[11];
    const float* be_1  = (const float*)d_in[12];
    const float* W2_1  = (const float*)d_in[13];
    const float* b2_1  = (const float*)d_in[14];

    const int4* src4 = (const int4*)ei;
    const int4* dst4 = (const int4*)(ei + EE);

    __half* z16;
    float *u, *W2p, *b2p;
    int *cur;
    cudaGetSymbolAddress((void**)&z16, g_z16);
    cudaGetSymbolAddress((void**)&u, g_u);
    cudaGetSymbolAddress((void**)&W2p, g_W2p);
    cudaGetSymbolAddress((void**)&b2p, g_b2p);
    cudaGetSymbolAddress((void**)&cur, g_cur);

    float* out  = (float*)d_out;
    float* xg   = out;            // (G, 64)
    float* hout = out + GG * 64;  // (N, 64)

    const int edge4_blocks = (EE / 4 + 255) / 256;
    const int node_blocks  = NN / 8;           // 12500

    // ---------- CSR build (rank-capture) ----------
    cudaMemsetAsync(cur, 0, NN * sizeof(int));
    hist_kernel<<<edge4_blocks, 256>>>(dst4);
    scan_kernel<<<1, 1024>>>(xg);                     // + zero statsP, xg

    // ---------- layer 0 (gemm0 carries the atomic-free scatter tail) ----------
    gemm0_scatter<<<GEMM_BLOCKS, 128>>>(x, W1_0, z16, NN, src4, dst4);
    gather_post<<<node_blocks, 256>>>(z16, b1_0, u);
    bn_finalize<<<1, 256>>>(g_0, be_0, W2_0, b2_0);
    gemm_mid<<<GEMM_BLOCKS, 128>>>(u, W2p, b2p, W1_1, z16, NN);

    // ---------- layer 1 ----------
    gather_post<<<node_blocks, 256>>>(z16, b1_1, u);
    bn_finalize<<<1, 256>>>(g_1, be_1, W2_1, b2_1);
    gemm_final<<<GEMM_BLOCKS, 128>>>(u, W2p, b2p, hout, batch, xg, NN);
}